// round 2
// baseline (speedup 1.0000x reference)
#include <cuda_runtime.h>

// ---------------------------------------------------------------------------
// WeightedTP: tp[n,w] = sum_k sum_{uv} h[n,k] * c[n,uv] * W2[k, uv*128+w]
// with symmetrized uv-pairs (u<=v): Wsym = W[uv]+W[vu], 272 pairs (2 paths x 136).
// Bias we_b2 folded in as k=64 row with h=1.
// Pipeline: repack(Wsym) -> prep(h, c) -> tp (FFMA2 contraction) -> out (om MLP)
// ---------------------------------------------------------------------------

#define MAXN 2048
#define NK 65            // 64 hidden rows + 1 bias row
#define NJ 272           // 2 paths * 136 unordered pairs
#define NW 128

#define PATH_COEFF 0.04419417382415922f   // 1/sqrt(512)
#define CG110      0.57735026918962576f   // 1/sqrt(3)
#define LN_EPS     1e-5f

typedef unsigned long long ull;

__device__ float g_h[MAXN * 64];
__device__ float g_c[MAXN * NJ];
__device__ float g_wsym[NK * NJ * NW];
__device__ float g_tp[2 * MAXN * NW];   // 2 k-splits, summed in epilogue

// ---- packed f32x2 helpers (sm_103a) ----
__device__ __forceinline__ ull pack2(float x, float y) {
    ull r;
    asm("mov.b64 %0, {%1, %2};" : "=l"(r) : "f"(x), "f"(y));
    return r;
}
__device__ __forceinline__ void unpack2(ull v, float& x, float& y) {
    asm("mov.b64 {%0, %1}, %2;" : "=f"(x), "=f"(y) : "l"(v));
}
__device__ __forceinline__ ull ffma2(ull a, ull b, ull c) {
    ull d;
    asm("fma.rn.f32x2 %0, %1, %2, %3;" : "=l"(d) : "l"(a), "l"(b), "l"(c));
    return d;
}

__device__ __forceinline__ float silu_f(float v) {
    return v / (1.0f + __expf(-v));
}

// ---------------------------------------------------------------------------
// Kernel 1: build Wsym[k][jj][w]; jj = p*136 + tri(u,v), u<=v.
// ---------------------------------------------------------------------------
__global__ void repack_kernel(const float* __restrict__ w2,
                              const float* __restrict__ b2) {
    int idx = blockIdx.x * blockDim.x + threadIdx.x;
    const int total = NK * NJ * NW;
    if (idx >= total) return;
    int w    = idx & 127;
    int rest = idx >> 7;
    int jj   = rest % NJ;
    int k    = rest / NJ;
    int p = jj / 136;
    int q = jj % 136;
    int u = 0;
    while (q >= 16 - u) { q -= 16 - u; u++; }
    int v = u + q;
    const float* src = (k < 64) ? (w2 + (size_t)k * 65536) : b2;
    float val = src[((p * 256 + u * 16 + v) << 7) + w];
    if (u != v) val += src[((p * 256 + v * 16 + u) << 7) + w];
    g_wsym[idx] = val;
}

// ---------------------------------------------------------------------------
// Kernel 2: per-row prep — h[n][64] = silu(LN(feats)@we_w1), c[n][272].
// One warp per row, 8 rows per 256-thread block.
// ---------------------------------------------------------------------------
__global__ void prep_kernel(const float* __restrict__ x,
                            const float* __restrict__ lng,
                            const float* __restrict__ lnb,
                            const float* __restrict__ w1,
                            int N) {
    __shared__ float xs[8][64];
    __shared__ float lns[8][16];
    int warp = threadIdx.x >> 5;
    int lane = threadIdx.x & 31;
    int n = blockIdx.x * 8 + warp;
    if (n >= N) return;

    xs[warp][lane]      = x[(size_t)n * 64 + lane];
    xs[warp][lane + 32] = x[(size_t)n * 64 + 32 + lane];
    __syncwarp();

    // LayerNorm over the first 16 features
    float f = (lane < 16) ? xs[warp][lane] : 0.0f;
    float s = f;
    #pragma unroll
    for (int o = 16; o; o >>= 1) s += __shfl_xor_sync(0xffffffffu, s, o);
    float mu = s * (1.0f / 16.0f);
    float d = (lane < 16) ? (f - mu) : 0.0f;
    float ss = d * d;
    #pragma unroll
    for (int o = 16; o; o >>= 1) ss += __shfl_xor_sync(0xffffffffu, ss, o);
    float rstd = rsqrtf(ss * (1.0f / 16.0f) + LN_EPS);
    if (lane < 16) lns[warp][lane] = d * rstd * lng[lane] + lnb[lane];
    __syncwarp();

    // h = silu(ln @ w1), w1 is (16, 64)
    #pragma unroll
    for (int t = 0; t < 2; t++) {
        int j = lane + 32 * t;
        float acc = 0.0f;
        #pragma unroll
        for (int i = 0; i < 16; i++) acc += lns[warp][i] * w1[i * 64 + j];
        g_h[(size_t)n * 64 + j] = silu_f(acc);
    }

    // c coefficients over unordered pairs (u<=v), both paths, PATH_COEFF folded
    for (int t = lane; t < NJ; t += 32) {
        int p = t / 136;
        int q = t % 136;
        int u = 0;
        int qq = q;
        while (qq >= 16 - u) { qq -= 16 - u; u++; }
        int v = u + qq;
        float val;
        if (p == 0) {
            val = PATH_COEFF * xs[warp][u] * xs[warp][v];
        } else {
            const float* a = &xs[warp][16 + u * 3];
            const float* b = &xs[warp][16 + v * 3];
            val = PATH_COEFF * CG110 * (a[0] * b[0] + a[1] * b[1] + a[2] * b[2]);
        }
        g_c[(size_t)n * NJ + t] = val;
    }
}

// ---------------------------------------------------------------------------
// Kernel 3: main contraction. Grid (N/16, 2 k-splits), 256 threads.
// Thread = (w-quad lw = tid&31, row-pair mp = tid>>5). FFMA2 inner loop.
// ---------------------------------------------------------------------------
__global__ __launch_bounds__(256) void tp_kernel(int N) {
    __shared__ float2 c_dup[NJ * 16];   // (v, v) duplicated per (jj, m)
    __shared__ float  h_sm[33 * 16];

    int tid   = threadIdx.x;
    int base  = blockIdx.x * 16;
    int split = blockIdx.y;
    int k0 = split ? 33 : 0;
    int k1 = split ? 65 : 33;
    int kcount = k1 - k0;

    for (int s = tid; s < NJ * 16; s += 256) {
        int jj = s >> 4, m = s & 15;
        float v = g_c[(size_t)(base + m) * NJ + jj];
        c_dup[s] = make_float2(v, v);
    }
    for (int s = tid; s < kcount * 16; s += 256) {
        int kl = s >> 4, m = s & 15;
        int k = k0 + kl;
        h_sm[s] = (k == 64) ? 1.0f : g_h[(size_t)(base + m) * 64 + k];
    }
    __syncthreads();

    int lw = tid & 31;
    int mp = tid >> 5;
    int m0 = mp * 2;

    const longlong2* Wv = reinterpret_cast<const longlong2*>(g_wsym);
    const ull* cdup = reinterpret_cast<const ull*>(c_dup);
    size_t wbase = ((size_t)k0 * NJ) * 32 + lw;

    ull acc00 = 0, acc01 = 0, acc10 = 0, acc11 = 0;

    for (int kl = 0; kl < kcount; kl++) {
        ull p00 = 0, p01 = 0, p10 = 0, p11 = 0;
        #pragma unroll 4
        for (int j = 0; j < NJ; j++) {
            longlong2 wv = Wv[wbase + (size_t)j * 32];
            ull w01 = (ull)wv.x;
            ull w23 = (ull)wv.y;
            ull cxx = cdup[j * 16 + m0];
            ull cyy = cdup[j * 16 + m0 + 1];
            p00 = ffma2(cxx, w01, p00);
            p01 = ffma2(cxx, w23, p01);
            p10 = ffma2(cyy, w01, p10);
            p11 = ffma2(cyy, w23, p11);
        }
        wbase += (size_t)NJ * 32;
        float h0 = h_sm[kl * 16 + m0];
        float h1 = h_sm[kl * 16 + m0 + 1];
        ull h00 = pack2(h0, h0);
        ull h11 = pack2(h1, h1);
        acc00 = ffma2(h00, p00, acc00);
        acc01 = ffma2(h00, p01, acc01);
        acc10 = ffma2(h11, p10, acc10);
        acc11 = ffma2(h11, p11, acc11);
    }

    float4 o0, o1;
    unpack2(acc00, o0.x, o0.y); unpack2(acc01, o0.z, o0.w);
    unpack2(acc10, o1.x, o1.y); unpack2(acc11, o1.z, o1.w);

    float4* out4 = reinterpret_cast<float4*>(g_tp);
    out4[(size_t)((size_t)split * N + base + m0) * 32 + lw]     = o0;
    out4[(size_t)((size_t)split * N + base + m0 + 1) * 32 + lw] = o1;
}

// ---------------------------------------------------------------------------
// Kernel 4: epilogue — sum splits, LN(128), silu(@om_w1 (128x512)), @om_w2 (512x1)+b.
// 8 rows per 128-thread block.
// ---------------------------------------------------------------------------
__global__ __launch_bounds__(128) void out_kernel(const float* __restrict__ lng,
                                                  const float* __restrict__ lnb,
                                                  const float* __restrict__ w1,
                                                  const float* __restrict__ w2,
                                                  const float* __restrict__ b2,
                                                  float* __restrict__ out,
                                                  int N) {
    __shared__ float ln_sm[8][128];
    __shared__ float part_sm[8][128];
    int tid  = threadIdx.x;
    int lane = tid & 31;
    int warp = tid >> 5;
    int rowbase = blockIdx.x * 8;

    // Phase A: sum k-splits + LayerNorm; each warp handles 2 rows
    for (int rr = 0; rr < 2; rr++) {
        int r = warp * 2 + rr;
        int g = rowbase + r;
        float v[4];
        #pragma unroll
        for (int t = 0; t < 4; t++) {
            int i = lane + 32 * t;
            v[t] = g_tp[(size_t)g * 128 + i] + g_tp[((size_t)N + g) * 128 + i];
        }
        float s = v[0] + v[1] + v[2] + v[3];
        #pragma unroll
        for (int o = 16; o; o >>= 1) s += __shfl_xor_sync(0xffffffffu, s, o);
        float mu = s * (1.0f / 128.0f);
        float ss = 0.0f;
        #pragma unroll
        for (int t = 0; t < 4; t++) { float d = v[t] - mu; ss += d * d; }
        #pragma unroll
        for (int o = 16; o; o >>= 1) ss += __shfl_xor_sync(0xffffffffu, ss, o);
        float rstd = rsqrtf(ss * (1.0f / 128.0f) + LN_EPS);
        #pragma unroll
        for (int t = 0; t < 4; t++) {
            int i = lane + 32 * t;
            ln_sm[r][i] = (v[t] - mu) * rstd * lng[i] + lnb[i];
        }
    }
    __syncthreads();

    // Phase B: hidden = ln @ om_w1; thread owns j-quad tid*4..tid*4+3 for 8 rows
    float y[8][4];
    #pragma unroll
    for (int r = 0; r < 8; r++)
        #pragma unroll
        for (int q = 0; q < 4; q++) y[r][q] = 0.0f;

    const float4* w1v = reinterpret_cast<const float4*>(w1);
    #pragma unroll 4
    for (int i = 0; i < 128; i++) {
        float4 wv = w1v[i * 128 + tid];
        #pragma unroll
        for (int r = 0; r < 8; r++) {
            float l = ln_sm[r][i];
            y[r][0] += l * wv.x;
            y[r][1] += l * wv.y;
            y[r][2] += l * wv.z;
            y[r][3] += l * wv.w;
        }
    }

    // Phase C: silu + dot with om_w2, reduce across threads
    float4 w2v = reinterpret_cast<const float4*>(w2)[tid];
    #pragma unroll
    for (int r = 0; r < 8; r++) {
        float s = silu_f(y[r][0]) * w2v.x + silu_f(y[r][1]) * w2v.y +
                  silu_f(y[r][2]) * w2v.z + silu_f(y[r][3]) * w2v.w;
        part_sm[r][tid] = s;
    }
    __syncthreads();

    if (tid < 8) {
        float s = 0.0f;
        #pragma unroll 4
        for (int i = 0; i < 128; i++) s += part_sm[tid][i];
        out[rowbase + tid] = s + b2[0];
    }
}

// ---------------------------------------------------------------------------
extern "C" void kernel_launch(void* const* d_in, const int* in_sizes, int n_in,
                              void* d_out, int out_size) {
    const float* x        = (const float*)d_in[0];
    const float* we_ln_g  = (const float*)d_in[1];
    const float* we_ln_b  = (const float*)d_in[2];
    const float* we_w1    = (const float*)d_in[3];
    const float* we_w2    = (const float*)d_in[4];
    const float* we_b2    = (const float*)d_in[5];
    const float* om_ln_g  = (const float*)d_in[6];
    const float* om_ln_b  = (const float*)d_in[7];
    const float* om_w1    = (const float*)d_in[8];
    const float* om_w2    = (const float*)d_in[9];
    const float* om_b2    = (const float*)d_in[10];

    int N = in_sizes[0] / 64;
    if (N > MAXN) N = MAXN;

    const int total = NK * NJ * NW;
    repack_kernel<<<(total + 255) / 256, 256>>>(we_w2, we_b2);
    prep_kernel<<<(N + 7) / 8, 256>>>(x, we_ln_g, we_ln_b, we_w1, N);
    tp_kernel<<<dim3(N / 16, 2), 256>>>(N);
    out_kernel<<<N / 8, 128>>>(om_ln_g, om_ln_b, om_w1, om_w2, om_b2,
                               (float*)d_out, N);
}

// round 3
// speedup vs baseline: 3.1951x; 3.1951x over previous
#include <cuda_runtime.h>

// ---------------------------------------------------------------------------
// WeightedTP: tp[n,w] = sum_k sum_{j} h[n,k] * c[n,j] * Wsym[k,j,w]
// j = symmetrized uv-pairs (u<=v), 272 = 2 paths x 136. Bias as k=64, h=1.
// R3: tp_kernel with 4 rows/thread (16 MAC per W-load), broadcast LDS.128 of
// non-duplicated c, 8 k-splits (512 CTAs), transposed g_cT/g_hT for coalesced
// smem fill. out_kernel: 4 rows/block (512 blocks) + warp-reduce.
// ---------------------------------------------------------------------------

#define MAXN 2048
#define NK 65            // 64 hidden rows + 1 bias row
#define NJ 272           // 2 paths * 136 unordered pairs
#define NW 128
#define KSPLIT 8

#define PATH_COEFF 0.04419417382415922f   // 1/sqrt(512)
#define CG110      0.57735026918962576f   // 1/sqrt(3)
#define LN_EPS     1e-5f

typedef unsigned long long ull;

__device__ float g_hT[64 * MAXN];          // [k][n]
__device__ float g_cT[NJ * MAXN];          // [j][n]
__device__ float g_wsym[NK * NJ * NW];     // [k][j][w]
__device__ float g_tp[KSPLIT * MAXN * NW]; // k-split partials

// ---- packed f32x2 helpers (sm_103a) ----
__device__ __forceinline__ ull pack2(float x, float y) {
    ull r;
    asm("mov.b64 %0, {%1, %2};" : "=l"(r) : "f"(x), "f"(y));
    return r;
}
__device__ __forceinline__ void unpack2(ull v, float& x, float& y) {
    asm("mov.b64 {%0, %1}, %2;" : "=f"(x), "=f"(y) : "l"(v));
}
__device__ __forceinline__ ull ffma2(ull a, ull b, ull c) {
    ull d;
    asm("fma.rn.f32x2 %0, %1, %2, %3;" : "=l"(d) : "l"(a), "l"(b), "l"(c));
    return d;
}

__device__ __forceinline__ float silu_f(float v) {
    return v / (1.0f + __expf(-v));
}

// ---------------------------------------------------------------------------
// Kernel 1: build Wsym[k][jj][w]; jj = p*136 + tri(u,v), u<=v.
// ---------------------------------------------------------------------------
__global__ void repack_kernel(const float* __restrict__ w2,
                              const float* __restrict__ b2) {
    int idx = blockIdx.x * blockDim.x + threadIdx.x;
    const int total = NK * NJ * NW;
    if (idx >= total) return;
    int w    = idx & 127;
    int rest = idx >> 7;
    int jj   = rest % NJ;
    int k    = rest / NJ;
    int p = jj / 136;
    int q = jj % 136;
    int u = 0;
    while (q >= 16 - u) { q -= 16 - u; u++; }
    int v = u + q;
    const float* src = (k < 64) ? (w2 + (size_t)k * 65536) : b2;
    float val = src[((p * 256 + u * 16 + v) << 7) + w];
    if (u != v) val += src[((p * 256 + v * 16 + u) << 7) + w];
    g_wsym[idx] = val;
}

// ---------------------------------------------------------------------------
// Kernel 2: per-row prep — h (transposed), c (transposed).
// One warp per row, 8 rows per 256-thread block.
// ---------------------------------------------------------------------------
__global__ void prep_kernel(const float* __restrict__ x,
                            const float* __restrict__ lng,
                            const float* __restrict__ lnb,
                            const float* __restrict__ w1,
                            int N) {
    __shared__ float xs[8][64];
    __shared__ float lns[8][16];
    int warp = threadIdx.x >> 5;
    int lane = threadIdx.x & 31;
    int n = blockIdx.x * 8 + warp;
    if (n >= N) return;

    xs[warp][lane]      = x[(size_t)n * 64 + lane];
    xs[warp][lane + 32] = x[(size_t)n * 64 + 32 + lane];
    __syncwarp();

    // LayerNorm over the first 16 features
    float f = (lane < 16) ? xs[warp][lane] : 0.0f;
    float s = f;
    #pragma unroll
    for (int o = 16; o; o >>= 1) s += __shfl_xor_sync(0xffffffffu, s, o);
    float mu = s * (1.0f / 16.0f);
    float d = (lane < 16) ? (f - mu) : 0.0f;
    float ss = d * d;
    #pragma unroll
    for (int o = 16; o; o >>= 1) ss += __shfl_xor_sync(0xffffffffu, ss, o);
    float rstd = rsqrtf(ss * (1.0f / 16.0f) + LN_EPS);
    if (lane < 16) lns[warp][lane] = d * rstd * lng[lane] + lnb[lane];
    __syncwarp();

    // h = silu(ln @ w1), w1 is (16, 64); store transposed [k][n]
    #pragma unroll
    for (int t = 0; t < 2; t++) {
        int j = lane + 32 * t;
        float acc = 0.0f;
        #pragma unroll
        for (int i = 0; i < 16; i++) acc += lns[warp][i] * w1[i * 64 + j];
        g_hT[(size_t)j * MAXN + n] = silu_f(acc);
    }

    // c coefficients over unordered pairs (u<=v), PATH_COEFF folded; transposed [j][n]
    for (int t = lane; t < NJ; t += 32) {
        int p = t / 136;
        int q = t % 136;
        int u = 0;
        int qq = q;
        while (qq >= 16 - u) { qq -= 16 - u; u++; }
        int v = u + qq;
        float val;
        if (p == 0) {
            val = PATH_COEFF * xs[warp][u] * xs[warp][v];
        } else {
            const float* a = &xs[warp][16 + u * 3];
            const float* b = &xs[warp][16 + v * 3];
            val = PATH_COEFF * CG110 * (a[0] * b[0] + a[1] * b[1] + a[2] * b[2]);
        }
        g_cT[(size_t)t * MAXN + n] = val;
    }
}

// ---------------------------------------------------------------------------
// Kernel 3: main contraction. Grid (N/32, KSPLIT), 256 threads.
// Thread = (w-quad lw, 4 rows m0..m0+3). 16 MACs per 16B W-load.
// ---------------------------------------------------------------------------
__global__ __launch_bounds__(256) void tp_kernel(int N) {
    __shared__ float c_sm[NJ * 32];   // [j][m], non-duplicated
    __shared__ float h_sm[9 * 32];    // [kl][m]

    int tid   = threadIdx.x;
    int base  = blockIdx.x * 32;
    int split = blockIdx.y;
    int k0 = (split * NK) / KSPLIT;
    int k1 = ((split + 1) * NK) / KSPLIT;
    int kc = k1 - k0;

    for (int s = tid; s < NJ * 32; s += 256)
        c_sm[s] = g_cT[(size_t)(s >> 5) * MAXN + base + (s & 31)];
    for (int s = tid; s < kc * 32; s += 256) {
        int k = k0 + (s >> 5);
        h_sm[s] = (k == 64) ? 1.0f : g_hT[(size_t)k * MAXN + base + (s & 31)];
    }
    __syncthreads();

    int lw = tid & 31;
    int m0 = (tid >> 5) * 4;
    int mq = m0 >> 2;

    const longlong2* Wv = reinterpret_cast<const longlong2*>(g_wsym)
                          + (size_t)k0 * NJ * 32 + lw;
    const float4* c4p = reinterpret_cast<const float4*>(c_sm);

    ull acc[8];
    #pragma unroll
    for (int i = 0; i < 8; i++) acc[i] = 0;

    for (int k = k0; k < k1; k++) {
        ull p[8];
        #pragma unroll
        for (int i = 0; i < 8; i++) p[i] = 0;

        #pragma unroll 4
        for (int j = 0; j < NJ; j++) {
            longlong2 wv = Wv[(size_t)j * 32];
            float4 c4 = c4p[j * 8 + mq];          // broadcast, conflict-free
            ull w01 = (ull)wv.x;
            ull w23 = (ull)wv.y;
            ull cd;
            cd = pack2(c4.x, c4.x);
            p[0] = ffma2(cd, w01, p[0]);
            p[1] = ffma2(cd, w23, p[1]);
            cd = pack2(c4.y, c4.y);
            p[2] = ffma2(cd, w01, p[2]);
            p[3] = ffma2(cd, w23, p[3]);
            cd = pack2(c4.z, c4.z);
            p[4] = ffma2(cd, w01, p[4]);
            p[5] = ffma2(cd, w23, p[5]);
            cd = pack2(c4.w, c4.w);
            p[6] = ffma2(cd, w01, p[6]);
            p[7] = ffma2(cd, w23, p[7]);
        }
        Wv += (size_t)NJ * 32;

        #pragma unroll
        for (int r = 0; r < 4; r++) {
            float h = h_sm[(k - k0) * 32 + m0 + r];
            ull hd = pack2(h, h);
            acc[2 * r]     = ffma2(hd, p[2 * r],     acc[2 * r]);
            acc[2 * r + 1] = ffma2(hd, p[2 * r + 1], acc[2 * r + 1]);
        }
    }

    float4* out4 = reinterpret_cast<float4*>(g_tp);
    #pragma unroll
    for (int r = 0; r < 4; r++) {
        float4 o;
        unpack2(acc[2 * r],     o.x, o.y);
        unpack2(acc[2 * r + 1], o.z, o.w);
        out4[((size_t)split * N + base + m0 + r) * 32 + lw] = o;
    }
}

// ---------------------------------------------------------------------------
// Kernel 4: epilogue — sum splits, LN(128), silu(@om_w1), @om_w2 + b.
// 4 rows per 128-thread block (one row per warp in phase A/C).
// ---------------------------------------------------------------------------
__global__ __launch_bounds__(128) void out_kernel(const float* __restrict__ lng,
                                                  const float* __restrict__ lnb,
                                                  const float* __restrict__ w1,
                                                  const float* __restrict__ w2,
                                                  const float* __restrict__ b2,
                                                  float* __restrict__ out,
                                                  int N) {
    __shared__ float ln_sm[4][128];
    __shared__ float part_sm[4][128];
    int tid  = threadIdx.x;
    int lane = tid & 31;
    int warp = tid >> 5;
    int rowbase = blockIdx.x * 4;

    // Phase A: sum k-splits + LayerNorm; one row per warp
    {
        int g = rowbase + warp;
        float v[4];
        #pragma unroll
        for (int t = 0; t < 4; t++) {
            int i = lane + 32 * t;
            float s = 0.0f;
            #pragma unroll
            for (int sp = 0; sp < KSPLIT; sp++)
                s += g_tp[((size_t)sp * N + g) * 128 + i];
            v[t] = s;
        }
        float s = v[0] + v[1] + v[2] + v[3];
        #pragma unroll
        for (int o = 16; o; o >>= 1) s += __shfl_xor_sync(0xffffffffu, s, o);
        float mu = s * (1.0f / 128.0f);
        float ss = 0.0f;
        #pragma unroll
        for (int t = 0; t < 4; t++) { float d = v[t] - mu; ss += d * d; }
        #pragma unroll
        for (int o = 16; o; o >>= 1) ss += __shfl_xor_sync(0xffffffffu, ss, o);
        float rstd = rsqrtf(ss * (1.0f / 128.0f) + LN_EPS);
        #pragma unroll
        for (int t = 0; t < 4; t++) {
            int i = lane + 32 * t;
            ln_sm[warp][i] = (v[t] - mu) * rstd * lng[i] + lnb[i];
        }
    }
    __syncthreads();

    // Phase B: hidden = ln @ om_w1; thread owns j-quad tid*4..tid*4+3, 4 rows
    float y[4][4];
    #pragma unroll
    for (int r = 0; r < 4; r++)
        #pragma unroll
        for (int q = 0; q < 4; q++) y[r][q] = 0.0f;

    const float4* w1v = reinterpret_cast<const float4*>(w1);
    #pragma unroll 8
    for (int i = 0; i < 128; i++) {
        float4 wv = w1v[i * 128 + tid];
        #pragma unroll
        for (int r = 0; r < 4; r++) {
            float l = ln_sm[r][i];
            y[r][0] += l * wv.x;
            y[r][1] += l * wv.y;
            y[r][2] += l * wv.z;
            y[r][3] += l * wv.w;
        }
    }

    // Phase C: silu + dot with om_w2
    float4 w2v = reinterpret_cast<const float4*>(w2)[tid];
    #pragma unroll
    for (int r = 0; r < 4; r++) {
        float s = silu_f(y[r][0]) * w2v.x + silu_f(y[r][1]) * w2v.y +
                  silu_f(y[r][2]) * w2v.z + silu_f(y[r][3]) * w2v.w;
        part_sm[r][tid] = s;
    }
    __syncthreads();

    // Warp r reduces row r
    {
        float s = part_sm[warp][lane] + part_sm[warp][lane + 32] +
                  part_sm[warp][lane + 64] + part_sm[warp][lane + 96];
        #pragma unroll
        for (int o = 16; o; o >>= 1) s += __shfl_xor_sync(0xffffffffu, s, o);
        if (lane == 0) out[rowbase + warp] = s + b2[0];
    }
}

// ---------------------------------------------------------------------------
extern "C" void kernel_launch(void* const* d_in, const int* in_sizes, int n_in,
                              void* d_out, int out_size) {
    const float* x        = (const float*)d_in[0];
    const float* we_ln_g  = (const float*)d_in[1];
    const float* we_ln_b  = (const float*)d_in[2];
    const float* we_w1    = (const float*)d_in[3];
    const float* we_w2    = (const float*)d_in[4];
    const float* we_b2    = (const float*)d_in[5];
    const float* om_ln_g  = (const float*)d_in[6];
    const float* om_ln_b  = (const float*)d_in[7];
    const float* om_w1    = (const float*)d_in[8];
    const float* om_w2    = (const float*)d_in[9];
    const float* om_b2    = (const float*)d_in[10];

    int N = in_sizes[0] / 64;
    if (N > MAXN) N = MAXN;

    const int total = NK * NJ * NW;
    repack_kernel<<<(total + 255) / 256, 256>>>(we_w2, we_b2);
    prep_kernel<<<(N + 7) / 8, 256>>>(x, we_ln_g, we_ln_b, we_w1, N);
    tp_kernel<<<dim3(N / 32, KSPLIT), 256>>>(N);
    out_kernel<<<N / 4, 128>>>(om_ln_g, om_ln_b, om_w1, om_w2, om_b2,
                               (float*)d_out, N);
}